// round 15
// baseline (speedup 1.0000x reference)
#include <cuda_runtime.h>
#include <cuda_fp16.h>
#include <math.h>
#include <stdint.h>

#define NTOK 4096
#define DMODEL 1024
#define NH 16
#define TSEQ 1024

// ---------------- helpers ----------------
__device__ __forceinline__ uint32_t smem_u32(const void* p) {
    uint32_t a;
    asm("{ .reg .u64 t; cvta.to.shared.u64 t, %1; cvt.u32.u64 %0, t; }" : "=r"(a) : "l"(p));
    return a;
}

#define LDSM4(r, addr) \
    asm volatile("ldmatrix.sync.aligned.m8n8.x4.shared.b16 {%0,%1,%2,%3}, [%4];" \
        : "=r"((r)[0]), "=r"((r)[1]), "=r"((r)[2]), "=r"((r)[3]) : "r"(addr))

#define LDSM4T(r, addr) \
    asm volatile("ldmatrix.sync.aligned.m8n8.x4.trans.shared.b16 {%0,%1,%2,%3}, [%4];" \
        : "=r"((r)[0]), "=r"((r)[1]), "=r"((r)[2]), "=r"((r)[3]) : "r"(addr))

#define MMAH(c, a, b) \
    asm volatile("mma.sync.aligned.m16n8k16.row.col.f32.f16.f16.f32 " \
        "{%0,%1,%2,%3}, {%4,%5,%6,%7}, {%8,%9}, {%0,%1,%2,%3};" \
        : "+f"((c)[0]), "+f"((c)[1]), "+f"((c)[2]), "+f"((c)[3]) \
        : "r"((a)[0]), "r"((a)[1]), "r"((a)[2]), "r"((a)[3]), "r"((b)[0]), "r"((b)[1]))

#define CP_ASYNC16(dst, src) \
    asm volatile("cp.async.cg.shared.global [%0], [%1], 16;" :: "r"(dst), "l"(src) : "memory")
#define CP_COMMIT() asm volatile("cp.async.commit_group;" ::: "memory")
#define CP_WAIT0()  asm volatile("cp.async.wait_group 0;" ::: "memory")
#define CP_WAIT1()  asm volatile("cp.async.wait_group 1;" ::: "memory")

// ---------------- scratch (device globals) ----------------
__device__ __align__(256) __half g_x16[(size_t)NTOK * DMODEL];
__device__ __align__(256) __half g_wqkv16[(size_t)4 * 3072 * 1024];
__device__ __align__(256) __half g_wo16[(size_t)4 * 1024 * 1024];
__device__ __align__(256) __half g_wg16[(size_t)4096 * 4096];
__device__ __align__(256) __half g_wout16[(size_t)1024 * 4096];
__device__ __align__(256) __half g_qkv16[(size_t)4 * NTOK * 3072];
__device__ __align__(256) __half g_attn16[(size_t)4 * NTOK * 1024];
__device__ __align__(256) __half g_conc16[(size_t)NTOK * 4096];
__device__ __align__(256) __half g_gat16[(size_t)NTOK * 4096];
__device__ __align__(256) float g_fused[(size_t)NTOK * 1024];

// ---------------- fp32 -> fp16 converts ----------------
__global__ __launch_bounds__(256) void convert_fp16(
    const float* __restrict__ in, __half* __restrict__ o, int n)
{
    const int n4 = n >> 2;
    for (int i = blockIdx.x * 256 + threadIdx.x; i < n4; i += gridDim.x * 256) {
        float4 v = ((const float4*)in)[i];
        __half2 p[2];
        p[0] = __floats2half2_rn(v.x, v.y);
        p[1] = __floats2half2_rn(v.z, v.w);
        ((uint2*)o)[i] = *(uint2*)p;
    }
}

struct CvtBatch { const float* src[4]; __half* dst[4]; };

__global__ __launch_bounds__(256) void convert_fp16_b4(CvtBatch p, int n)
{
    const float* __restrict__ in = p.src[blockIdx.z];
    __half* __restrict__ o = p.dst[blockIdx.z];
    const int n4 = n >> 2;
    for (int i = blockIdx.x * 256 + threadIdx.x; i < n4; i += gridDim.x * 256) {
        float4 v = ((const float4*)in)[i];
        __half2 q[2];
        q[0] = __floats2half2_rn(v.x, v.y);
        q[1] = __floats2half2_rn(v.z, v.w);
        ((uint2*)o)[i] = *(uint2*)q;
    }
}

// =================================================================================
// HMMA fp16 single-term GEMM (proven): CTA 128x128, K-step 32, 3-stage (48KB).
// mode 0: Cf = acc; mode 1: C16 = fp16(acc); mode 2: sigmoid-gate epilogue
// Batched over blockIdx.z: A += z*sA, B += z*sB, C16 += z*sC, coff += z*sCoff.
// =================================================================================
#define HSTAGEB 16384
#define HSMEM   (3 * HSTAGEB)

__device__ __forceinline__ void load_stage_h(
    const __half* __restrict__ A, const __half* __restrict__ B,
    int K, int k0, int bm, int bn, uint32_t sstage, int tid)
{
#pragma unroll
    for (int it = 0; it < 4; it++) {
        int cidx = tid + it * 256;
        int t = cidx >> 9;
        int row = (cidx >> 2) & 127;
        int c = cidx & 3;
        const __half* src = t ? B : A;
        int rb = t ? bn : bm;
        const __half* gsrc = src + (size_t)(rb + row) * K + k0 + c * 8;
        uint32_t dst = sstage + t * 8192 + row * 64 + ((c ^ ((row >> 1) & 3)) << 4);
        CP_ASYNC16(dst, gsrc);
    }
    CP_COMMIT();
}

__global__ __launch_bounds__(256, 2) void gemm_fp16(
    const __half* __restrict__ A, const __half* __restrict__ B,
    int K, int mode,
    float* __restrict__ Cf, __half* __restrict__ C16,
    const float* __restrict__ bias, const __half* __restrict__ X16,
    int ldc, int coff, size_t sA, size_t sB, size_t sC, int sCoff)
{
    extern __shared__ char smem[];
    const uint32_t sb = smem_u32(smem);
    const int tid = threadIdx.x;
    const int wid = tid >> 5, lane = tid & 31;
    const int bm = blockIdx.y * 128;
    const int bn = blockIdx.x * 128;
    const int z = blockIdx.z;
    A += (size_t)z * sA; B += (size_t)z * sB;
    if (C16) C16 += (size_t)z * sC;
    coff += z * sCoff;
    const int wm = (wid >> 2) * 64;
    const int wn = (wid & 3) * 32;

    float acc[4][4][4];
#pragma unroll
    for (int mi = 0; mi < 4; mi++)
#pragma unroll
        for (int nj = 0; nj < 4; nj++)
#pragma unroll
            for (int q = 0; q < 4; q++) acc[mi][nj][q] = 0.f;

    const int nchunk = K >> 5;
    load_stage_h(A, B, K, 0, bm, bn, sb, tid);
    load_stage_h(A, B, K, 32, bm, bn, sb + HSTAGEB, tid);

    int slot = 0;
    for (int i = 0; i < nchunk; i++) {
        if (i + 1 < nchunk) CP_WAIT1(); else CP_WAIT0();
        __syncthreads();
        if (i + 2 < nchunk) {
            int ns = slot + 2; if (ns >= 3) ns -= 3;
            load_stage_h(A, B, K, (i + 2) << 5, bm, bn, sb + ns * HSTAGEB, tid);
        }

        const uint32_t st = sb + slot * HSTAGEB;
#pragma unroll
        for (int ks = 0; ks < 2; ks++) {
            uint32_t ah[4][4], bh[2][4];
#pragma unroll
            for (int mi = 0; mi < 4; mi++) {
                int row = wm + mi * 16 + (lane & 15);
                int ch = (lane >> 4) + ks * 2;
                uint32_t ad = st + row * 64 + ((ch ^ ((row >> 1) & 3)) << 4);
                LDSM4(ah[mi], ad);
            }
#pragma unroll
            for (int nb = 0; nb < 2; nb++) {
                int row = wn + nb * 16 + (lane & 7) + ((lane >> 4) << 3);
                int ch = ((lane >> 3) & 1) + ks * 2;
                uint32_t ad = st + 8192 + row * 64 + ((ch ^ ((row >> 1) & 3)) << 4);
                LDSM4(bh[nb], ad);
            }
#pragma unroll
            for (int mi = 0; mi < 4; mi++)
#pragma unroll
                for (int nj = 0; nj < 4; nj++) {
                    uint32_t* bhp = &bh[nj >> 1][(nj & 1) * 2];
                    MMAH(acc[mi][nj], ah[mi], bhp);
                }
        }
        if (++slot >= 3) slot = 0;
    }

    // epilogue
#pragma unroll
    for (int mi = 0; mi < 4; mi++) {
#pragma unroll
        for (int r = 0; r < 2; r++) {
            int m = bm + wm + mi * 16 + (lane >> 2) + r * 8;
#pragma unroll
            for (int nj = 0; nj < 4; nj++) {
                int n = bn + wn + nj * 8 + (lane & 3) * 2;
                float v0 = acc[mi][nj][r * 2 + 0];
                float v1 = acc[mi][nj][r * 2 + 1];
                size_t o = (size_t)m * ldc + coff + n;
                if (mode == 0) {
                    *(float2*)(Cf + o) = make_float2(v0, v1);
                } else if (mode == 1) {
                    *(__half2*)(C16 + o) = __floats2half2_rn(v0, v1);
                } else {
                    float g0 = 1.f / (1.f + __expf(-(v0 + bias[n])));
                    float g1 = 1.f / (1.f + __expf(-(v1 + bias[n + 1])));
                    float a0 = __half2float(X16[o]);
                    float a1 = __half2float(X16[o + 1]);
                    *(__half2*)(C16 + o) = __floats2half2_rn(g0 * a0, g1 * a1);
                }
            }
        }
    }
}

// =================================================================================
// Flash attention, HMMA fp16, double-buffered K/V, 128-row q-tiles (8 warps).
// Smem: Q 16KB, K/V x2 slots 32KB, P 16KB = 64KB. All 4 directions via blockIdx.z.
// Per-warp compute identical to the proven 64-row version (16 q-rows/warp).
// =================================================================================
#define ATTN_SMEM 65536

__global__ __launch_bounds__(256) void attn_kernel(
    const __half* __restrict__ qkv16, __half* __restrict__ attn16)
{
    extern __shared__ char smem[];
    const uint32_t sb = smem_u32(smem);
    const int dir = blockIdx.z;
    const int tr = dir >= 2, rev = dir & 1;
    const __half* qkv = qkv16 + (size_t)dir * NTOK * 3072;
    __half* attn = attn16 + (size_t)dir * NTOK * 1024;
    const int qt = blockIdx.x;            // 128-row q tile (0..7)
    const int b  = blockIdx.y >> 4;
    const int h  = blockIdx.y & 15;
    const int tid = threadIdx.x;
    const int wid = tid >> 5, lane = tid & 31;   // wid 0..7
    const size_t bq = (size_t)b * TSEQ;
    const uint32_t sQ = sb, sKV = sb + 16384, sP = sb + 49152;

    // ---- load Q: 128 rows (scaled by 1/8, permuted gather) ----
    {
        const __half2 s2 = __floats2half2_rn(0.125f, 0.125f);
        for (int i = tid; i < 1024; i += 256) {
            int row = i >> 3, c = i & 7;
            int t = qt * 128 + row;
            int tok = tr ? ((t & 31) * 32 + (t >> 5)) : t;
            uint4 v = *(const uint4*)(qkv + (bq + tok) * 3072 + h * 64 + c * 8);
            __half2* p2 = (__half2*)&v;
#pragma unroll
            for (int q = 0; q < 4; q++) p2[q] = __hmul2(p2[q], s2);
            *(uint4*)(smem + row * 128 + ((c ^ (row & 7)) << 4)) = v;
        }
    }

    float m0[2] = {-1e30f, -1e30f}, l0[2] = {0.f, 0.f};
    float o[8][4];
#pragma unroll
    for (int nj = 0; nj < 8; nj++)
#pragma unroll
        for (int q = 0; q < 4; q++) o[nj][q] = 0.f;

    const int kt_lo = rev ? 2 * qt : 0;
    const int kt_hi = rev ? 15 : 2 * qt + 1;

    // prologue: load first K/V tile into slot 0
    {
        int kt = kt_lo;
        for (int i = tid; i < 1024; i += 256) {
            int arr = i >> 9;              // 0:K 1:V
            int j = i & 511;
            int row = j >> 3, c = j & 7;
            int t = kt * 64 + row;
            int tok = tr ? ((t & 31) * 32 + (t >> 5)) : t;
            const __half* src = qkv + (bq + tok) * 3072 + 1024 + arr * 1024 + h * 64 + c * 8;
            CP_ASYNC16(sKV + arr * 8192 + row * 128 + ((c ^ (row & 7)) << 4), src);
        }
        CP_COMMIT();
    }

    int cur = 0;
    for (int kt = kt_lo; kt <= kt_hi; kt++) {
        if (kt + 1 <= kt_hi) {
            __syncthreads();   // all warps done with slot cur^1 (used 2 iters ago)
            int nxt = cur ^ 1;
            int kn = kt + 1;
            for (int i = tid; i < 1024; i += 256) {
                int arr = i >> 9;
                int j = i & 511;
                int row = j >> 3, c = j & 7;
                int t = kn * 64 + row;
                int tok = tr ? ((t & 31) * 32 + (t >> 5)) : t;
                const __half* src = qkv + (bq + tok) * 3072 + 1024 + arr * 1024 + h * 64 + c * 8;
                CP_ASYNC16(sKV + nxt * 16384 + arr * 8192 + row * 128 + ((c ^ (row & 7)) << 4), src);
            }
            CP_COMMIT();
            CP_WAIT1();
        } else {
            CP_WAIT0();
        }
        __syncthreads();

        const uint32_t sK = sKV + cur * 16384;
        const uint32_t sV = sK + 8192;

        // ---- S = Q K^T ----
        float s[8][4];
#pragma unroll
        for (int nj = 0; nj < 8; nj++)
#pragma unroll
            for (int q = 0; q < 4; q++) s[nj][q] = 0.f;
#pragma unroll
        for (int kk = 0; kk < 4; kk++) {
            uint32_t q_f[4];
            {
                int row = wid * 16 + (lane & 15);   // 0..127
                int ch = (lane >> 4) + kk * 2;
                LDSM4(q_f, sQ + row * 128 + ((ch ^ (row & 7)) << 4));
            }
#pragma unroll
            for (int nb = 0; nb < 4; nb++) {
                uint32_t k_f[4];
                int row = nb * 16 + (lane & 7) + ((lane >> 4) << 3);
                int ch = ((lane >> 3) & 1) + kk * 2;
                LDSM4(k_f, sK + row * 128 + ((ch ^ (row & 7)) << 4));
#pragma unroll
                for (int half = 0; half < 2; half++)
                    MMAH(s[nb * 2 + half], q_f, (&k_f[half * 2]));
            }
        }

        // ---- mask (straddle tiles: kv tile within this 128-row q block) ----
        if ((kt >> 1) == qt) {
#pragma unroll
            for (int nj = 0; nj < 8; nj++)
#pragma unroll
                for (int q = 0; q < 4; q++) {
                    int rr = q >> 1;
                    int qi = qt * 128 + wid * 16 + (lane >> 2) + rr * 8;
                    int ki = kt * 64 + nj * 8 + (lane & 3) * 2 + (q & 1);
                    bool valid = rev ? (ki >= qi) : (ki <= qi);
                    if (!valid) s[nj][q] = -1e30f;
                }
        }

        // ---- online softmax + P write (fp16; own rows only) ----
#pragma unroll
        for (int rr = 0; rr < 2; rr++) {
            float vm = -1e30f;
#pragma unroll
            for (int nj = 0; nj < 8; nj++) {
                vm = fmaxf(vm, s[nj][rr * 2 + 0]);
                vm = fmaxf(vm, s[nj][rr * 2 + 1]);
            }
            vm = fmaxf(vm, __shfl_xor_sync(0xffffffffu, vm, 1));
            vm = fmaxf(vm, __shfl_xor_sync(0xffffffffu, vm, 2));
            float mn = fmaxf(m0[rr], vm);
            float fac = __expf(m0[rr] - mn);
            float rs = 0.f;
            int qrow = wid * 16 + (lane >> 2) + rr * 8;   // 0..127
#pragma unroll
            for (int nj = 0; nj < 8; nj++) {
                float p0 = __expf(s[nj][rr * 2 + 0] - mn);
                float p1 = __expf(s[nj][rr * 2 + 1] - mn);
                rs += p0 + p1;
                uint32_t off = qrow * 128 + ((nj ^ (qrow & 7)) << 4) + (lane & 3) * 4;
                *(__half2*)(smem + (sP - sb) + off) = __floats2half2_rn(p0, p1);
            }
            rs += __shfl_xor_sync(0xffffffffu, rs, 1);
            rs += __shfl_xor_sync(0xffffffffu, rs, 2);
            l0[rr] = l0[rr] * fac + rs;
            m0[rr] = mn;
#pragma unroll
            for (int nj = 0; nj < 8; nj++) {
                o[nj][rr * 2 + 0] *= fac;
                o[nj][rr * 2 + 1] *= fac;
            }
        }

        // ---- O += P V ----
#pragma unroll
        for (int kk = 0; kk < 4; kk++) {
            uint32_t p_f[4];
            {
                int row = wid * 16 + (lane & 15);
                int ch = (lane >> 4) + kk * 2;
                LDSM4(p_f, sP + row * 128 + ((ch ^ (row & 7)) << 4));
            }
#pragma unroll
            for (int nb = 0; nb < 4; nb++) {
                uint32_t v_f[4];
                int row = kk * 16 + (lane & 15);
                int ch = (nb * 2 + (lane >> 4)) ^ (row & 7);
                LDSM4T(v_f, sV + row * 128 + (ch << 4));
#pragma unroll
                for (int half = 0; half < 2; half++)
                    MMAH(o[nb * 2 + half], p_f, (&v_f[half * 2]));
            }
        }
        cur ^= 1;
    }

    // ---- normalize + permuted scatter (fp16) ----
#pragma unroll
    for (int rr = 0; rr < 2; rr++) {
        float inv = 1.f / l0[rr];
        int qrow = wid * 16 + (lane >> 2) + rr * 8;
        int t = qt * 128 + qrow;
        int tok = tr ? ((t & 31) * 32 + (t >> 5)) : t;
        size_t base = (bq + tok) * 1024 + h * 64;
#pragma unroll
        for (int nj = 0; nj < 8; nj++) {
            int d = nj * 8 + (lane & 3) * 2;
            *(__half2*)(attn + base + d) =
                __floats2half2_rn(o[nj][rr * 2 + 0] * inv, o[nj][rr * 2 + 1] * inv);
        }
    }
}

// =================================================================================
// RMSNorm epilogue
// =================================================================================
__global__ __launch_bounds__(256) void rmsnorm_kernel(
    const float* __restrict__ fused, const float* __restrict__ x,
    const float* __restrict__ w, float* __restrict__ out)
{
    const int t = blockIdx.x;
    const int tid = threadIdx.x;
    const float* fr = fused + (size_t)t * 1024;
    const float* xr = x + (size_t)t * 1024;
    float y[4];
    float ss = 0.f;
#pragma unroll
    for (int i = 0; i < 4; i++) {
        int c = tid + i * 256;
        y[i] = fr[c] + xr[c];
        ss += y[i] * y[i];
    }
#pragma unroll
    for (int off = 16; off >= 1; off >>= 1)
        ss += __shfl_xor_sync(0xffffffffu, ss, off);
    __shared__ float red[8];
    if ((tid & 31) == 0) red[tid >> 5] = ss;
    __syncthreads();
    float tot = red[0] + red[1] + red[2] + red[3] + red[4] + red[5] + red[6] + red[7];
    float r = rsqrtf(tot * (1.f / 1024.f) + 1e-6f);
    float* orow = out + (size_t)t * 1024;
#pragma unroll
    for (int i = 0; i < 4; i++) {
        int c = tid + i * 256;
        orow[c] = y[i] * r * w[c];
    }
}

// =================================================================================
// Launch
// =================================================================================
extern "C" void kernel_launch(void* const* d_in, const int* in_sizes, int n_in,
                              void* d_out, int out_size)
{
    const float* x       = (const float*)d_in[0];
    const float* w_qkv[4] = { (const float*)d_in[1], (const float*)d_in[3],
                              (const float*)d_in[5], (const float*)d_in[7] };
    const float* w_o[4]   = { (const float*)d_in[2], (const float*)d_in[4],
                              (const float*)d_in[6], (const float*)d_in[8] };
    const float* w_gate  = (const float*)d_in[9];
    const float* b_gate  = (const float*)d_in[10];
    const float* w_out   = (const float*)d_in[11];
    const float* norm_w  = (const float*)d_in[12];
    float* out = (float*)d_out;

    __half *x16, *wqkv16, *wo16, *wg16, *wout16, *qkv16, *attn16, *conc16, *gat16;
    float *fused;
    cudaGetSymbolAddress((void**)&x16, g_x16);
    cudaGetSymbolAddress((void**)&wqkv16, g_wqkv16);
    cudaGetSymbolAddress((void**)&wo16, g_wo16);
    cudaGetSymbolAddress((void**)&wg16, g_wg16);
    cudaGetSymbolAddress((void**)&wout16, g_wout16);
    cudaGetSymbolAddress((void**)&qkv16, g_qkv16);
    cudaGetSymbolAddress((void**)&attn16, g_attn16);
    cudaGetSymbolAddress((void**)&conc16, g_conc16);
    cudaGetSymbolAddress((void**)&gat16, g_gat16);
    cudaGetSymbolAddress((void**)&fused, g_fused);

    cudaFuncSetAttribute(attn_kernel, cudaFuncAttributeMaxDynamicSharedMemorySize, ATTN_SMEM);
    cudaFuncSetAttribute(gemm_fp16, cudaFuncAttributeMaxDynamicSharedMemorySize, HSMEM);

    // converts (batched)
    convert_fp16<<<1024, 256>>>(x, x16, NTOK * DMODEL);
    {
        CvtBatch cb;
        for (int d = 0; d < 4; d++) { cb.src[d] = w_qkv[d]; cb.dst[d] = wqkv16 + (size_t)d * 3072 * 1024; }
        convert_fp16_b4<<<dim3(1024, 1, 4), 256>>>(cb, 3072 * 1024);
    }
    {
        CvtBatch cb;
        for (int d = 0; d < 4; d++) { cb.src[d] = w_o[d]; cb.dst[d] = wo16 + (size_t)d * 1024 * 1024; }
        convert_fp16_b4<<<dim3(512, 1, 4), 256>>>(cb, 1024 * 1024);
    }
    convert_fp16<<<4096, 256>>>(w_gate, wg16, 4096 * 4096);
    convert_fp16<<<2048, 256>>>(w_out, wout16, 1024 * 4096);

    // QKV, all 4 directions batched: x16 @ wqkv16[z]^T -> qkv16[z]
    gemm_fp16<<<dim3(3072 / 128, 4096 / 128, 4), 256, HSMEM>>>(
        x16, wqkv16, 1024, 1, nullptr, qkv16, nullptr, nullptr,
        3072, 0, 0, (size_t)3072 * 1024, (size_t)NTOK * 3072, 0);

    // attention, all directions in one launch (128-row q tiles)
    attn_kernel<<<dim3(8, 4 * NH, 4), 256, ATTN_SMEM>>>(qkv16, attn16);

    // O-proj, batched: attn16[z] @ wo16[z]^T -> conc16[:, z*1024 + ...]
    gemm_fp16<<<dim3(1024 / 128, 4096 / 128, 4), 256, HSMEM>>>(
        attn16, wo16, 1024, 1, nullptr, conc16, nullptr, nullptr,
        4096, 0, (size_t)NTOK * 1024, (size_t)1024 * 1024, 0, 1024);

    // gate: sigmoid(conc16 @ wg16^T + b) * conc16 -> gat16
    gemm_fp16<<<dim3(4096 / 128, 4096 / 128), 256, HSMEM>>>(
        conc16, wg16, 4096, 2, nullptr, gat16, b_gate, conc16,
        4096, 0, 0, 0, 0, 0);

    // out: gat16 @ wout16^T -> fused fp32
    gemm_fp16<<<dim3(1024 / 128, 4096 / 128), 256, HSMEM>>>(
        gat16, wout16, 4096, 0, fused, nullptr, nullptr, nullptr,
        1024, 0, 0, 0, 0, 0);

    rmsnorm_kernel<<<NTOK, 256>>>(fused, x, norm_w, out);
}

// round 16
// speedup vs baseline: 1.0298x; 1.0298x over previous
#include <cuda_runtime.h>
#include <cuda_fp16.h>
#include <math.h>
#include <stdint.h>

#define NTOK 4096
#define DMODEL 1024
#define NH 16
#define TSEQ 1024

// ---------------- helpers ----------------
__device__ __forceinline__ uint32_t smem_u32(const void* p) {
    uint32_t a;
    asm("{ .reg .u64 t; cvta.to.shared.u64 t, %1; cvt.u32.u64 %0, t; }" : "=r"(a) : "l"(p));
    return a;
}

#define LDSM4(r, addr) \
    asm volatile("ldmatrix.sync.aligned.m8n8.x4.shared.b16 {%0,%1,%2,%3}, [%4];" \
        : "=r"((r)[0]), "=r"((r)[1]), "=r"((r)[2]), "=r"((r)[3]) : "r"(addr))

#define LDSM4T(r, addr) \
    asm volatile("ldmatrix.sync.aligned.m8n8.x4.trans.shared.b16 {%0,%1,%2,%3}, [%4];" \
        : "=r"((r)[0]), "=r"((r)[1]), "=r"((r)[2]), "=r"((r)[3]) : "r"(addr))

#define MMAH(c, a, b) \
    asm volatile("mma.sync.aligned.m16n8k16.row.col.f32.f16.f16.f32 " \
        "{%0,%1,%2,%3}, {%4,%5,%6,%7}, {%8,%9}, {%0,%1,%2,%3};" \
        : "+f"((c)[0]), "+f"((c)[1]), "+f"((c)[2]), "+f"((c)[3]) \
        : "r"((a)[0]), "r"((a)[1]), "r"((a)[2]), "r"((a)[3]), "r"((b)[0]), "r"((b)[1]))

#define CP_ASYNC16(dst, src) \
    asm volatile("cp.async.cg.shared.global [%0], [%1], 16;" :: "r"(dst), "l"(src) : "memory")
#define CP_COMMIT() asm volatile("cp.async.commit_group;" ::: "memory")
#define CP_WAIT0()  asm volatile("cp.async.wait_group 0;" ::: "memory")
#define CP_WAIT1()  asm volatile("cp.async.wait_group 1;" ::: "memory")

// ---------------- scratch (device globals) ----------------
__device__ __align__(256) __half g_x16[(size_t)NTOK * DMODEL];
__device__ __align__(256) __half g_wqkv16[(size_t)4 * 3072 * 1024];
__device__ __align__(256) __half g_wo16[(size_t)4 * 1024 * 1024];
__device__ __align__(256) __half g_wg16[(size_t)4096 * 4096];
__device__ __align__(256) __half g_wout16[(size_t)1024 * 4096];
__device__ __align__(256) __half g_qkv16[(size_t)4 * NTOK * 3072];
__device__ __align__(256) __half g_attn16[(size_t)4 * NTOK * 1024];
__device__ __align__(256) __half g_conc16[(size_t)NTOK * 4096];
__device__ __align__(256) __half g_gat16[(size_t)NTOK * 4096];
__device__ __align__(256) float g_fused[(size_t)NTOK * 1024];

// ---------------- fp32 -> fp16 converts ----------------
__global__ __launch_bounds__(256) void convert_fp16(
    const float* __restrict__ in, __half* __restrict__ o, int n)
{
    const int n4 = n >> 2;
    for (int i = blockIdx.x * 256 + threadIdx.x; i < n4; i += gridDim.x * 256) {
        float4 v = ((const float4*)in)[i];
        __half2 p[2];
        p[0] = __floats2half2_rn(v.x, v.y);
        p[1] = __floats2half2_rn(v.z, v.w);
        ((uint2*)o)[i] = *(uint2*)p;
    }
}

struct CvtBatch { const float* src[4]; __half* dst[4]; };

__global__ __launch_bounds__(256) void convert_fp16_b4(CvtBatch p, int n)
{
    const float* __restrict__ in = p.src[blockIdx.z];
    __half* __restrict__ o = p.dst[blockIdx.z];
    const int n4 = n >> 2;
    for (int i = blockIdx.x * 256 + threadIdx.x; i < n4; i += gridDim.x * 256) {
        float4 v = ((const float4*)in)[i];
        __half2 q[2];
        q[0] = __floats2half2_rn(v.x, v.y);
        q[1] = __floats2half2_rn(v.z, v.w);
        ((uint2*)o)[i] = *(uint2*)q;
    }
}

// =================================================================================
// HMMA fp16 single-term GEMM (proven): CTA 128x128, K-step 32, 3-stage (48KB).
// mode 0: Cf = acc; mode 1: C16 = fp16(acc); mode 2: sigmoid-gate epilogue
// Batched over blockIdx.z: A += z*sA, B += z*sB, C16 += z*sC, coff += z*sCoff.
// =================================================================================
#define HSTAGEB 16384
#define HSMEM   (3 * HSTAGEB)

__device__ __forceinline__ void load_stage_h(
    const __half* __restrict__ A, const __half* __restrict__ B,
    int K, int k0, int bm, int bn, uint32_t sstage, int tid)
{
#pragma unroll
    for (int it = 0; it < 4; it++) {
        int cidx = tid + it * 256;
        int t = cidx >> 9;
        int row = (cidx >> 2) & 127;
        int c = cidx & 3;
        const __half* src = t ? B : A;
        int rb = t ? bn : bm;
        const __half* gsrc = src + (size_t)(rb + row) * K + k0 + c * 8;
        uint32_t dst = sstage + t * 8192 + row * 64 + ((c ^ ((row >> 1) & 3)) << 4);
        CP_ASYNC16(dst, gsrc);
    }
    CP_COMMIT();
}

__global__ __launch_bounds__(256, 2) void gemm_fp16(
    const __half* __restrict__ A, const __half* __restrict__ B,
    int K, int mode,
    float* __restrict__ Cf, __half* __restrict__ C16,
    const float* __restrict__ bias, const __half* __restrict__ X16,
    int ldc, int coff, size_t sA, size_t sB, size_t sC, int sCoff)
{
    extern __shared__ char smem[];
    const uint32_t sb = smem_u32(smem);
    const int tid = threadIdx.x;
    const int wid = tid >> 5, lane = tid & 31;
    const int bm = blockIdx.y * 128;
    const int bn = blockIdx.x * 128;
    const int z = blockIdx.z;
    A += (size_t)z * sA; B += (size_t)z * sB;
    if (C16) C16 += (size_t)z * sC;
    coff += z * sCoff;
    const int wm = (wid >> 2) * 64;
    const int wn = (wid & 3) * 32;

    float acc[4][4][4];
#pragma unroll
    for (int mi = 0; mi < 4; mi++)
#pragma unroll
        for (int nj = 0; nj < 4; nj++)
#pragma unroll
            for (int q = 0; q < 4; q++) acc[mi][nj][q] = 0.f;

    const int nchunk = K >> 5;
    load_stage_h(A, B, K, 0, bm, bn, sb, tid);
    load_stage_h(A, B, K, 32, bm, bn, sb + HSTAGEB, tid);

    int slot = 0;
    for (int i = 0; i < nchunk; i++) {
        if (i + 1 < nchunk) CP_WAIT1(); else CP_WAIT0();
        __syncthreads();
        if (i + 2 < nchunk) {
            int ns = slot + 2; if (ns >= 3) ns -= 3;
            load_stage_h(A, B, K, (i + 2) << 5, bm, bn, sb + ns * HSTAGEB, tid);
        }

        const uint32_t st = sb + slot * HSTAGEB;
#pragma unroll
        for (int ks = 0; ks < 2; ks++) {
            uint32_t ah[4][4], bh[2][4];
#pragma unroll
            for (int mi = 0; mi < 4; mi++) {
                int row = wm + mi * 16 + (lane & 15);
                int ch = (lane >> 4) + ks * 2;
                uint32_t ad = st + row * 64 + ((ch ^ ((row >> 1) & 3)) << 4);
                LDSM4(ah[mi], ad);
            }
#pragma unroll
            for (int nb = 0; nb < 2; nb++) {
                int row = wn + nb * 16 + (lane & 7) + ((lane >> 4) << 3);
                int ch = ((lane >> 3) & 1) + ks * 2;
                uint32_t ad = st + 8192 + row * 64 + ((ch ^ ((row >> 1) & 3)) << 4);
                LDSM4(bh[nb], ad);
            }
#pragma unroll
            for (int mi = 0; mi < 4; mi++)
#pragma unroll
                for (int nj = 0; nj < 4; nj++) {
                    uint32_t* bhp = &bh[nj >> 1][(nj & 1) * 2];
                    MMAH(acc[mi][nj], ah[mi], bhp);
                }
        }
        if (++slot >= 3) slot = 0;
    }

    // epilogue
#pragma unroll
    for (int mi = 0; mi < 4; mi++) {
#pragma unroll
        for (int r = 0; r < 2; r++) {
            int m = bm + wm + mi * 16 + (lane >> 2) + r * 8;
#pragma unroll
            for (int nj = 0; nj < 4; nj++) {
                int n = bn + wn + nj * 8 + (lane & 3) * 2;
                float v0 = acc[mi][nj][r * 2 + 0];
                float v1 = acc[mi][nj][r * 2 + 1];
                size_t o = (size_t)m * ldc + coff + n;
                if (mode == 0) {
                    *(float2*)(Cf + o) = make_float2(v0, v1);
                } else if (mode == 1) {
                    *(__half2*)(C16 + o) = __floats2half2_rn(v0, v1);
                } else {
                    float g0 = 1.f / (1.f + __expf(-(v0 + bias[n])));
                    float g1 = 1.f / (1.f + __expf(-(v1 + bias[n + 1])));
                    float a0 = __half2float(X16[o]);
                    float a1 = __half2float(X16[o + 1]);
                    *(__half2*)(C16 + o) = __floats2half2_rn(g0 * a0, g1 * a1);
                }
            }
        }
    }
}

// =================================================================================
// Flash attention, HMMA fp16 single-term, double-buffered K/V (proven).
// Smem: Q 8KB, K/V x2 slots 32KB, P 8KB = 48KB. All 4 directions via blockIdx.z.
// =================================================================================
#define ATTN_SMEM 49152

__global__ __launch_bounds__(128) void attn_kernel(
    const __half* __restrict__ qkv16, __half* __restrict__ attn16)
{
    extern __shared__ char smem[];
    const uint32_t sb = smem_u32(smem);
    const int dir = blockIdx.z;
    const int tr = dir >= 2, rev = dir & 1;
    const __half* qkv = qkv16 + (size_t)dir * NTOK * 3072;
    __half* attn = attn16 + (size_t)dir * NTOK * 1024;
    const int qt = blockIdx.x;
    const int b  = blockIdx.y >> 4;
    const int h  = blockIdx.y & 15;
    const int tid = threadIdx.x;
    const int wid = tid >> 5, lane = tid & 31;
    const size_t bq = (size_t)b * TSEQ;
    const uint32_t sQ = sb, sKV = sb + 8192, sP = sb + 40960;

    // ---- load Q (scaled by 1/8, permuted gather) ----
    {
        const __half2 s2 = __floats2half2_rn(0.125f, 0.125f);
        for (int i = tid; i < 512; i += 128) {
            int row = i >> 3, c = i & 7;
            int t = qt * 64 + row;
            int tok = tr ? ((t & 31) * 32 + (t >> 5)) : t;
            uint4 v = *(const uint4*)(qkv + (bq + tok) * 3072 + h * 64 + c * 8);
            __half2* p2 = (__half2*)&v;
#pragma unroll
            for (int q = 0; q < 4; q++) p2[q] = __hmul2(p2[q], s2);
            *(uint4*)(smem + row * 128 + ((c ^ (row & 7)) << 4)) = v;
        }
    }

    float m0[2] = {-1e30f, -1e30f}, l0[2] = {0.f, 0.f};
    float o[8][4];
#pragma unroll
    for (int nj = 0; nj < 8; nj++)
#pragma unroll
        for (int q = 0; q < 4; q++) o[nj][q] = 0.f;

    const int kt_lo = rev ? qt : 0;
    const int kt_hi = rev ? 15 : qt;

    // prologue: load first K/V tile into slot 0
    {
        int kt = kt_lo;
        for (int i = tid; i < 1024; i += 128) {
            int arr = i >> 9;
            int j = i & 511;
            int row = j >> 3, c = j & 7;
            int t = kt * 64 + row;
            int tok = tr ? ((t & 31) * 32 + (t >> 5)) : t;
            const __half* src = qkv + (bq + tok) * 3072 + 1024 + arr * 1024 + h * 64 + c * 8;
            CP_ASYNC16(sKV + arr * 8192 + row * 128 + ((c ^ (row & 7)) << 4), src);
        }
        CP_COMMIT();
    }

    int cur = 0;
    for (int kt = kt_lo; kt <= kt_hi; kt++) {
        if (kt + 1 <= kt_hi) {
            __syncthreads();   // all warps done with slot cur^1 (used 2 iters ago)
            int nxt = cur ^ 1;
            int kn = kt + 1;
            for (int i = tid; i < 1024; i += 128) {
                int arr = i >> 9;
                int j = i & 511;
                int row = j >> 3, c = j & 7;
                int t = kn * 64 + row;
                int tok = tr ? ((t & 31) * 32 + (t >> 5)) : t;
                const __half* src = qkv + (bq + tok) * 3072 + 1024 + arr * 1024 + h * 64 + c * 8;
                CP_ASYNC16(sKV + nxt * 16384 + arr * 8192 + row * 128 + ((c ^ (row & 7)) << 4), src);
            }
            CP_COMMIT();
            CP_WAIT1();
        } else {
            CP_WAIT0();
        }
        __syncthreads();

        const uint32_t sK = sKV + cur * 16384;
        const uint32_t sV = sK + 8192;

        // ---- S = Q K^T ----
        float s[8][4];
#pragma unroll
        for (int nj = 0; nj < 8; nj++)
#pragma unroll
            for (int q = 0; q < 4; q++) s[nj][q] = 0.f;
#pragma unroll
        for (int kk = 0; kk < 4; kk++) {
            uint32_t q_f[4];
            {
                int row = wid * 16 + (lane & 15);
                int ch = (lane >> 4) + kk * 2;
                LDSM4(q_f, sQ + row * 128 + ((ch ^ (row & 7)) << 4));
            }
#pragma unroll
            for (int nb = 0; nb < 4; nb++) {
                uint32_t k_f[4];
                int row = nb * 16 + (lane & 7) + ((lane >> 4) << 3);
                int ch = ((lane >> 3) & 1) + kk * 2;
                LDSM4(k_f, sK + row * 128 + ((ch ^ (row & 7)) << 4));
#pragma unroll
                for (int half = 0; half < 2; half++)
                    MMAH(s[nb * 2 + half], q_f, (&k_f[half * 2]));
            }
        }

        // ---- mask (diagonal tile) ----
        if (kt == qt) {
#pragma unroll
            for (int nj = 0; nj < 8; nj++)
#pragma unroll
                for (int q = 0; q < 4; q++) {
                    int rr = q >> 1;
                    int qi = qt * 64 + wid * 16 + (lane >> 2) + rr * 8;
                    int ki = kt * 64 + nj * 8 + (lane & 3) * 2 + (q & 1);
                    bool valid = rev ? (ki >= qi) : (ki <= qi);
                    if (!valid) s[nj][q] = -1e30f;
                }
        }

        // ---- online softmax + P write (fp16; own rows only) ----
#pragma unroll
        for (int rr = 0; rr < 2; rr++) {
            float vm = -1e30f;
#pragma unroll
            for (int nj = 0; nj < 8; nj++) {
                vm = fmaxf(vm, s[nj][rr * 2 + 0]);
                vm = fmaxf(vm, s[nj][rr * 2 + 1]);
            }
            vm = fmaxf(vm, __shfl_xor_sync(0xffffffffu, vm, 1));
            vm = fmaxf(vm, __shfl_xor_sync(0xffffffffu, vm, 2));
            float mn = fmaxf(m0[rr], vm);
            float fac = __expf(m0[rr] - mn);
            float rs = 0.f;
            int qrow = wid * 16 + (lane >> 2) + rr * 8;
#pragma unroll
            for (int nj = 0; nj < 8; nj++) {
                float p0 = __expf(s[nj][rr * 2 + 0] - mn);
                float p1 = __expf(s[nj][rr * 2 + 1] - mn);
                rs += p0 + p1;
                uint32_t off = qrow * 128 + ((nj ^ (qrow & 7)) << 4) + (lane & 3) * 4;
                *(__half2*)(smem + (sP - sb) + off) = __floats2half2_rn(p0, p1);
            }
            rs += __shfl_xor_sync(0xffffffffu, rs, 1);
            rs += __shfl_xor_sync(0xffffffffu, rs, 2);
            l0[rr] = l0[rr] * fac + rs;
            m0[rr] = mn;
#pragma unroll
            for (int nj = 0; nj < 8; nj++) {
                o[nj][rr * 2 + 0] *= fac;
                o[nj][rr * 2 + 1] *= fac;
            }
        }

        // ---- O += P V ----
#pragma unroll
        for (int kk = 0; kk < 4; kk++) {
            uint32_t p_f[4];
            {
                int row = wid * 16 + (lane & 15);
                int ch = (lane >> 4) + kk * 2;
                LDSM4(p_f, sP + row * 128 + ((ch ^ (row & 7)) << 4));
            }
#pragma unroll
            for (int nb = 0; nb < 4; nb++) {
                uint32_t v_f[4];
                int row = kk * 16 + (lane & 15);
                int ch = (nb * 2 + (lane >> 4)) ^ (row & 7);
                LDSM4T(v_f, sV + row * 128 + (ch << 4));
#pragma unroll
                for (int half = 0; half < 2; half++)
                    MMAH(o[nb * 2 + half], p_f, (&v_f[half * 2]));
            }
        }
        cur ^= 1;
    }

    // ---- normalize + permuted scatter (fp16) ----
#pragma unroll
    for (int rr = 0; rr < 2; rr++) {
        float inv = 1.f / l0[rr];
        int qrow = wid * 16 + (lane >> 2) + rr * 8;
        int t = qt * 64 + qrow;
        int tok = tr ? ((t & 31) * 32 + (t >> 5)) : t;
        size_t base = (bq + tok) * 1024 + h * 64;
#pragma unroll
        for (int nj = 0; nj < 8; nj++) {
            int d = nj * 8 + (lane & 3) * 2;
            *(__half2*)(attn + base + d) =
                __floats2half2_rn(o[nj][rr * 2 + 0] * inv, o[nj][rr * 2 + 1] * inv);
        }
    }
}

// =================================================================================
// RMSNorm epilogue
// =================================================================================
__global__ __launch_bounds__(256) void rmsnorm_kernel(
    const float* __restrict__ fused, const float* __restrict__ x,
    const float* __restrict__ w, float* __restrict__ out)
{
    const int t = blockIdx.x;
    const int tid = threadIdx.x;
    const float* fr = fused + (size_t)t * 1024;
    const float* xr = x + (size_t)t * 1024;
    float y[4];
    float ss = 0.f;
#pragma unroll
    for (int i = 0; i < 4; i++) {
        int c = tid + i * 256;
        y[i] = fr[c] + xr[c];
        ss += y[i] * y[i];
    }
#pragma unroll
    for (int off = 16; off >= 1; off >>= 1)
        ss += __shfl_xor_sync(0xffffffffu, ss, off);
    __shared__ float red[8];
    if ((tid & 31) == 0) red[tid >> 5] = ss;
    __syncthreads();
    float tot = red[0] + red[1] + red[2] + red[3] + red[4] + red[5] + red[6] + red[7];
    float r = rsqrtf(tot * (1.f / 1024.f) + 1e-6f);
    float* orow = out + (size_t)t * 1024;
#pragma unroll
    for (int i = 0; i < 4; i++) {
        int c = tid + i * 256;
        orow[c] = y[i] * r * w[c];
    }
}

// =================================================================================
// Launch
// =================================================================================
extern "C" void kernel_launch(void* const* d_in, const int* in_sizes, int n_in,
                              void* d_out, int out_size)
{
    const float* x       = (const float*)d_in[0];
    const float* w_qkv[4] = { (const float*)d_in[1], (const float*)d_in[3],
                              (const float*)d_in[5], (const float*)d_in[7] };
    const float* w_o[4]   = { (const float*)d_in[2], (const float*)d_in[4],
                              (const float*)d_in[6], (const float*)d_in[8] };
    const float* w_gate  = (const float*)d_in[9];
    const float* b_gate  = (const float*)d_in[10];
    const float* w_out   = (const float*)d_in[11];
    const float* norm_w  = (const float*)d_in[12];
    float* out = (float*)d_out;

    __half *x16, *wqkv16, *wo16, *wg16, *wout16, *qkv16, *attn16, *conc16, *gat16;
    float *fused;
    cudaGetSymbolAddress((void**)&x16, g_x16);
    cudaGetSymbolAddress((void**)&wqkv16, g_wqkv16);
    cudaGetSymbolAddress((void**)&wo16, g_wo16);
    cudaGetSymbolAddress((void**)&wg16, g_wg16);
    cudaGetSymbolAddress((void**)&wout16, g_wout16);
    cudaGetSymbolAddress((void**)&qkv16, g_qkv16);
    cudaGetSymbolAddress((void**)&attn16, g_attn16);
    cudaGetSymbolAddress((void**)&conc16, g_conc16);
    cudaGetSymbolAddress((void**)&gat16, g_gat16);
    cudaGetSymbolAddress((void**)&fused, g_fused);

    cudaFuncSetAttribute(attn_kernel, cudaFuncAttributeMaxDynamicSharedMemorySize, ATTN_SMEM);
    cudaFuncSetAttribute(gemm_fp16, cudaFuncAttributeMaxDynamicSharedMemorySize, HSMEM);

    // converts (batched)
    convert_fp16<<<1024, 256>>>(x, x16, NTOK * DMODEL);
    {
        CvtBatch cb;
        for (int d = 0; d < 4; d++) { cb.src[d] = w_qkv[d]; cb.dst[d] = wqkv16 + (size_t)d * 3072 * 1024; }
        convert_fp16_b4<<<dim3(1024, 1, 4), 256>>>(cb, 3072 * 1024);
    }
    {
        CvtBatch cb;
        for (int d = 0; d < 4; d++) { cb.src[d] = w_o[d]; cb.dst[d] = wo16 + (size_t)d * 1024 * 1024; }
        convert_fp16_b4<<<dim3(512, 1, 4), 256>>>(cb, 1024 * 1024);
    }
    convert_fp16<<<4096, 256>>>(w_gate, wg16, 4096 * 4096);
    convert_fp16<<<2048, 256>>>(w_out, wout16, 1024 * 4096);

    // QKV, all 4 directions batched: x16 @ wqkv16[z]^T -> qkv16[z]
    gemm_fp16<<<dim3(3072 / 128, 4096 / 128, 4), 256, HSMEM>>>(
        x16, wqkv16, 1024, 1, nullptr, qkv16, nullptr, nullptr,
        3072, 0, 0, (size_t)3072 * 1024, (size_t)NTOK * 3072, 0);

    // attention, all directions in one launch
    attn_kernel<<<dim3(16, 4 * NH, 4), 128, ATTN_SMEM>>>(qkv16, attn16);

    // O-proj, batched: attn16[z] @ wo16[z]^T -> conc16[:, z*1024 + ...]
    gemm_fp16<<<dim3(1024 / 128, 4096 / 128, 4), 256, HSMEM>>>(
        attn16, wo16, 1024, 1, nullptr, conc16, nullptr, nullptr,
        4096, 0, (size_t)NTOK * 1024, (size_t)1024 * 1024, 0, 1024);

    // gate: sigmoid(conc16 @ wg16^T + b) * conc16 -> gat16
    gemm_fp16<<<dim3(4096 / 128, 4096 / 128), 256, HSMEM>>>(
        conc16, wg16, 4096, 2, nullptr, gat16, b_gate, conc16,
        4096, 0, 0, 0, 0, 0);

    // out: gat16 @ wout16^T -> fused fp32
    gemm_fp16<<<dim3(1024 / 128, 4096 / 128), 256, HSMEM>>>(
        gat16, wout16, 4096, 0, fused, nullptr, nullptr, nullptr,
        1024, 0, 0, 0, 0, 0);

    rmsnorm_kernel<<<NTOK, 256>>>(fused, x, norm_w, out);
}